// round 2
// baseline (speedup 1.0000x reference)
#include <cuda_runtime.h>
#include <cuda_bf16.h>
#include <cstdint>

// Problem constants (fixed by the dataset)
#define NN 50000
#define EE 800000
#define F_IN 128
#define HH 256
#define AA 5

// ----------------------------------------------------------------------------
// Scratch (static device memory; allocation inside kernel_launch is forbidden)
// ----------------------------------------------------------------------------
__device__ __align__(16) float g_buf0[(size_t)NN * HH];  // agg output
__device__ __align__(16) float g_buf1[(size_t)NN * HH];  // h1 / h2
__device__ int   g_cnt[NN];
__device__ int   g_rowptr[NN + 1];
__device__ int   g_cursor[NN];
__device__ int   g_csr[EE];
__device__ float g_dinv[NN];
__device__ float g_psum[HH];
__device__ float g_pmax[HH];

// ----------------------------------------------------------------------------
// init: zero counters + pooling accumulators
// ----------------------------------------------------------------------------
__global__ void k_init() {
    int i = blockIdx.x * blockDim.x + threadIdx.x;
    if (i < NN) g_cnt[i] = 0;
    if (i < HH) { g_psum[i] = 0.0f; g_pmax[i] = 0.0f; }
}

// count in-degrees (targets = edge_index[1])
__global__ void k_count(const int* __restrict__ col) {
    int e = blockIdx.x * blockDim.x + threadIdx.x;
    if (e < EE) atomicAdd(&g_cnt[col[e]], 1);
}

// dinv = rsqrt(deg + 1)  (self-loop included; always > 0)
__global__ void k_dinv() {
    int i = blockIdx.x * blockDim.x + threadIdx.x;
    if (i < NN) g_dinv[i] = rsqrtf((float)g_cnt[i] + 1.0f);
}

// single-block exclusive scan of g_cnt -> g_rowptr / g_cursor
__global__ void k_scan() {
    __shared__ int s[1024];
    int t = threadIdx.x;
    const int chunk = (NN + 1023) >> 10;  // 49
    int beg = t * chunk; if (beg > NN) beg = NN;
    int end = beg + chunk; if (end > NN) end = NN;
    int sum = 0;
    for (int i = beg; i < end; i++) sum += g_cnt[i];
    s[t] = sum;
    __syncthreads();
    // Hillis-Steele inclusive scan
    for (int off = 1; off < 1024; off <<= 1) {
        int v = (t >= off) ? s[t - off] : 0;
        __syncthreads();
        s[t] += v;
        __syncthreads();
    }
    int run = (t == 0) ? 0 : s[t - 1];
    for (int i = beg; i < end; i++) {
        g_rowptr[i] = run;
        g_cursor[i] = run;
        run += g_cnt[i];
    }
    if (t == 1023) g_rowptr[NN] = s[1023];
}

// scatter edges into CSR grouped by target
__global__ void k_fill(const int* __restrict__ row, const int* __restrict__ col) {
    int e = blockIdx.x * blockDim.x + threadIdx.x;
    if (e < EE) {
        int c = col[e];
        int p = atomicAdd(&g_cursor[c], 1);
        g_csr[p] = row[e];
    }
}

// ----------------------------------------------------------------------------
// Aggregation: out[c] = dinv[c] * ( dinv[c]*X[c] + sum_{r in in(c)} dinv[r]*X[r] )
// one block per node, one thread per feature (F = blockDim.x)
// ----------------------------------------------------------------------------
__global__ void k_agg(const float* __restrict__ X, float* __restrict__ out) {
    const int F = blockDim.x;
    const int c = blockIdx.x;
    const int j = threadIdx.x;
    const float dc = g_dinv[c];
    float acc = dc * X[(size_t)c * F + j];
    const int beg = g_rowptr[c];
    const int end = g_rowptr[c + 1];
    int r_next = (beg < end) ? g_csr[beg] : 0;
    for (int e = beg; e < end; e++) {
        int r = r_next;
        if (e + 1 < end) r_next = g_csr[e + 1];
        float dr = __ldg(&g_dinv[r]);
        acc += dr * __ldg(&X[(size_t)r * F + j]);
    }
    out[(size_t)c * F + j] = dc * acc;
}

// ----------------------------------------------------------------------------
// SGEMM: C = relu(A[M,K] @ B[K,Nc] + bias), fp32 SIMT
// 128x128x8 tiles, 256 threads, 8x8/thread with 4+4 split (conflict-free smem)
// ----------------------------------------------------------------------------
#define BM 128
#define BN 128
#define BK 8

__global__ __launch_bounds__(256) void k_sgemm_bias_relu(
    const float* __restrict__ A, const float* __restrict__ B,
    const float* __restrict__ bias, float* __restrict__ C,
    int M, int K, int Nc)
{
    __shared__ float As[BK][BM];
    __shared__ float Bs[BK][BN];

    const int tid = threadIdx.x;
    const int tx = tid & 15;       // 0..15 (col group)
    const int ty = tid >> 4;       // 0..15 (row group)
    const int rowBase = blockIdx.y * BM;
    const int colBase = blockIdx.x * BN;

    float acc[8][8];
#pragma unroll
    for (int i = 0; i < 8; i++)
#pragma unroll
        for (int j = 0; j < 8; j++) acc[i][j] = 0.0f;

    // A tile load mapping: 128x8 = 256 float4
    const int aRow = tid >> 1;
    const int aCol = (tid & 1) * 4;
    // B tile load mapping: 8x128 = 256 float4
    const int bRow = tid >> 5;
    const int bCol = (tid & 31) * 4;

    for (int k0 = 0; k0 < K; k0 += BK) {
        float4 av;
        int gr = rowBase + aRow;
        if (gr < M) av = *(const float4*)(A + (size_t)gr * K + k0 + aCol);
        else        av = make_float4(0.f, 0.f, 0.f, 0.f);
        As[aCol + 0][aRow] = av.x;
        As[aCol + 1][aRow] = av.y;
        As[aCol + 2][aRow] = av.z;
        As[aCol + 3][aRow] = av.w;

        float4 bv = *(const float4*)(B + (size_t)(k0 + bRow) * Nc + colBase + bCol);
        *(float4*)&Bs[bRow][bCol] = bv;
        __syncthreads();

#pragma unroll
        for (int k = 0; k < BK; k++) {
            float ar[8], br[8];
            float4 a0 = *(const float4*)&As[k][ty * 4];
            float4 a1 = *(const float4*)&As[k][64 + ty * 4];
            ar[0] = a0.x; ar[1] = a0.y; ar[2] = a0.z; ar[3] = a0.w;
            ar[4] = a1.x; ar[5] = a1.y; ar[6] = a1.z; ar[7] = a1.w;
            float4 b0 = *(const float4*)&Bs[k][tx * 4];
            float4 b1 = *(const float4*)&Bs[k][64 + tx * 4];
            br[0] = b0.x; br[1] = b0.y; br[2] = b0.z; br[3] = b0.w;
            br[4] = b1.x; br[5] = b1.y; br[6] = b1.z; br[7] = b1.w;
#pragma unroll
            for (int i = 0; i < 8; i++)
#pragma unroll
                for (int j = 0; j < 8; j++) acc[i][j] += ar[i] * br[j];
        }
        __syncthreads();
    }

    // epilogue: bias + relu, float4 stores
#pragma unroll
    for (int i = 0; i < 8; i++) {
        int r = rowBase + ((i < 4) ? (ty * 4 + i) : (64 + ty * 4 + i - 4));
        if (r >= M) continue;
#pragma unroll
        for (int half = 0; half < 2; half++) {
            int c = colBase + half * 64 + tx * 4;
            float4 v;
            int jb = half * 4;
            v.x = fmaxf(acc[i][jb + 0] + bias[c + 0], 0.0f);
            v.y = fmaxf(acc[i][jb + 1] + bias[c + 1], 0.0f);
            v.z = fmaxf(acc[i][jb + 2] + bias[c + 2], 0.0f);
            v.w = fmaxf(acc[i][jb + 3] + bias[c + 3], 0.0f);
            *(float4*)(C + (size_t)r * Nc + c) = v;
        }
    }
}

// ----------------------------------------------------------------------------
// Pooling: per-feature sum and max over all nodes (h >= 0 after relu, so
// int-compare atomicMax on the float bits is valid with 0-init).
// ----------------------------------------------------------------------------
#define POOL_ROWS 256
__global__ void k_pool(const float* __restrict__ h) {
    int j = threadIdx.x;                 // feature
    int r0 = blockIdx.x * POOL_ROWS;
    int r1 = r0 + POOL_ROWS; if (r1 > NN) r1 = NN;
    float s = 0.0f, m = 0.0f;
    for (int r = r0; r < r1; r++) {
        float v = h[(size_t)r * HH + j];
        s += v;
        m = fmaxf(m, v);
    }
    atomicAdd(&g_psum[j], s);
    atomicMax((int*)&g_pmax[j], __float_as_int(m));
}

// ----------------------------------------------------------------------------
// Head: out[a] = blin[a] + sum_j mean_j*W[j,a] + max_j*W[256+j,a] + sum_j*W[512+j,a]
// one warp per output
// ----------------------------------------------------------------------------
__global__ void k_final(const float* __restrict__ Wlin, const float* __restrict__ blin,
                        float* __restrict__ out) {
    int w = threadIdx.x >> 5;
    int lane = threadIdx.x & 31;
    if (w >= AA) return;
    const float invN = 1.0f / (float)NN;
    float acc = 0.0f;
    for (int j = lane; j < HH; j += 32) {
        float s = g_psum[j];
        float m = g_pmax[j];
        acc += s * invN * Wlin[(size_t)j * AA + w]
             + m        * Wlin[(size_t)(HH + j) * AA + w]
             + s        * Wlin[(size_t)(2 * HH + j) * AA + w];
    }
#pragma unroll
    for (int o = 16; o > 0; o >>= 1) acc += __shfl_down_sync(0xffffffffu, acc, o);
    if (lane == 0) out[w] = blin[w] + acc;
}

// ----------------------------------------------------------------------------
// Launch
// ----------------------------------------------------------------------------
extern "C" void kernel_launch(void* const* d_in, const int* in_sizes, int n_in,
                              void* d_out, int out_size) {
    const float* x    = (const float*)d_in[0];
    const int*   ei   = (const int*)d_in[1];      // int64 in reference -> int32 in harness
    const float* W1   = (const float*)d_in[2];
    const float* b1   = (const float*)d_in[3];
    const float* W2   = (const float*)d_in[4];
    const float* b2   = (const float*)d_in[5];
    const float* Wlin = (const float*)d_in[6];
    const float* blin = (const float*)d_in[7];
    float*       out  = (float*)d_out;

    const int* erow = ei;        // sources   edge_index[0]
    const int* ecol = ei + EE;   // targets   edge_index[1]

    float* buf0; cudaGetSymbolAddress((void**)&buf0, g_buf0);
    float* buf1; cudaGetSymbolAddress((void**)&buf1, g_buf1);

    // graph structure
    k_init<<<(NN + 255) / 256, 256>>>();
    k_count<<<(EE + 255) / 256, 256>>>(ecol);
    k_dinv<<<(NN + 255) / 256, 256>>>();
    k_scan<<<1, 1024>>>();
    k_fill<<<(EE + 255) / 256, 256>>>(erow, ecol);

    // layer 1: (A_hat x) @ W1 -> relu
    k_agg<<<NN, F_IN>>>(x, buf0);
    {
        dim3 grid(HH / BN, (NN + BM - 1) / BM);
        k_sgemm_bias_relu<<<grid, 256>>>(buf0, W1, b1, buf1, NN, F_IN, HH);
    }

    // layer 2: (A_hat h1) @ W2 -> relu
    k_agg<<<NN, HH>>>(buf1, buf0);
    {
        dim3 grid(HH / BN, (NN + BM - 1) / BM);
        k_sgemm_bias_relu<<<grid, 256>>>(buf0, W2, b2, buf1, NN, HH, HH);
    }

    // pooling + head
    k_pool<<<(NN + POOL_ROWS - 1) / POOL_ROWS, HH>>>(buf1);
    k_final<<<1, 160>>>(Wlin, blin, out);
}

// round 3
// speedup vs baseline: 1.6815x; 1.6815x over previous
#include <cuda_runtime.h>
#include <cstdint>

// Problem constants (fixed by the dataset)
#define NN 50000
#define EE 800000
#define F_IN 128
#define HH 256
#define AA 5

// ----------------------------------------------------------------------------
// Scratch (static device memory)
// ----------------------------------------------------------------------------
__device__ __align__(16) float g_buf0[(size_t)NN * HH];
__device__ __align__(16) float g_buf1[(size_t)NN * HH];
__device__ int   g_cnt[NN];
__device__ int   g_rowptr[NN + 1];
__device__ int   g_cursor[NN];
__device__ int   g_csr[EE];
__device__ float g_dinv[NN];
__device__ float g_psum[HH];
__device__ float g_pmax[HH];
__device__ int   g_bsum[256];
__device__ int   g_boff[256];

#define SCH 200   // elements per scan block
#define SBL 250   // scan blocks (250*200 = 50000)

// ----------------------------------------------------------------------------
// Graph build
// ----------------------------------------------------------------------------
__global__ void k_count(const int* __restrict__ col) {
    int e = blockIdx.x * blockDim.x + threadIdx.x;
    if (e < EE) atomicAdd(&g_cnt[col[e]], 1);
}

// per-block sums of g_cnt
__global__ void k_blocksum() {
    __shared__ int s[256];
    int t = threadIdx.x, b = blockIdx.x;
    int i = b * SCH + t;
    s[t] = (t < SCH && i < NN) ? g_cnt[i] : 0;
    __syncthreads();
    for (int o = 128; o > 0; o >>= 1) {
        if (t < o) s[t] += s[t + o];
        __syncthreads();
    }
    if (t == 0) g_bsum[b] = s[0];
}

// exclusive scan of block sums (1 block)
__global__ void k_scanbsum() {
    __shared__ int s[256];
    int t = threadIdx.x;
    s[t] = (t < SBL) ? g_bsum[t] : 0;
    __syncthreads();
    for (int o = 1; o < 256; o <<= 1) {
        int v = (t >= o) ? s[t - o] : 0;
        __syncthreads();
        s[t] += v;
        __syncthreads();
    }
    g_boff[t] = (t == 0) ? 0 : s[t - 1];
    if (t == 0) g_rowptr[NN] = EE;
}

// local scan + global offset -> rowptr/cursor; also dinv
__global__ void k_rowptr() {
    __shared__ int s[256];
    int t = threadIdx.x, b = blockIdx.x;
    int i = b * SCH + t;
    int c = (t < SCH && i < NN) ? g_cnt[i] : 0;
    s[t] = c;
    __syncthreads();
    for (int o = 1; o < 256; o <<= 1) {
        int v = (t >= o) ? s[t - o] : 0;
        __syncthreads();
        s[t] += v;
        __syncthreads();
    }
    if (t < SCH && i < NN) {
        int excl = g_boff[b] + s[t] - c;
        g_rowptr[i] = excl;
        g_cursor[i] = excl;
        g_dinv[i]   = rsqrtf((float)c + 1.0f);
    }
}

__global__ void k_fill(const int* __restrict__ row, const int* __restrict__ col) {
    int e = blockIdx.x * blockDim.x + threadIdx.x;
    if (e < EE) {
        int c = col[e];
        int p = atomicAdd(&g_cursor[c], 1);
        g_csr[p] = row[e];
    }
}

// ----------------------------------------------------------------------------
// Aggregation: out[c] = dinv[c] * ( dinv[c]*X[c] + sum_{r in in(c)} dinv[r]*X[r] )
// one block per node, one thread per feature
// ----------------------------------------------------------------------------
__global__ void k_agg(const float* __restrict__ X, float* __restrict__ out) {
    const int F = blockDim.x;
    const int c = blockIdx.x;
    const int j = threadIdx.x;
    const float dc = g_dinv[c];
    float acc = dc * X[(size_t)c * F + j];
    const int beg = g_rowptr[c];
    const int end = g_rowptr[c + 1];
    for (int e = beg; e < end; e++) {
        int r = g_csr[e];
        float dr = __ldg(&g_dinv[r]);
        acc += dr * __ldg(&X[(size_t)r * F + j]);
    }
    out[(size_t)c * F + j] = dc * acc;
}

// ----------------------------------------------------------------------------
// tf32 tensor-core GEMM: C = relu(A[M,K] @ B[K,Nc] + bias)
// block tile 128x128x16, 8 warps, warp tile 64x32, mma.m16n8k8.tf32
// ----------------------------------------------------------------------------
#define GP 136  // smem pitch (floats); 136 % 32 == 8 -> conflict-free frag loads

__device__ __forceinline__ unsigned f2t(float f) {
    unsigned u;
    asm("cvt.rna.tf32.f32 %0, %1;" : "=r"(u) : "f"(f));
    return u;
}

__device__ __forceinline__ void mma_tf32(float& c0, float& c1, float& c2, float& c3,
                                         unsigned a0, unsigned a1, unsigned a2, unsigned a3,
                                         unsigned b0, unsigned b1) {
    asm volatile(
        "mma.sync.aligned.m16n8k8.row.col.f32.tf32.tf32.f32 "
        "{%0,%1,%2,%3}, {%4,%5,%6,%7}, {%8,%9}, {%0,%1,%2,%3};"
        : "+f"(c0), "+f"(c1), "+f"(c2), "+f"(c3)
        : "r"(a0), "r"(a1), "r"(a2), "r"(a3), "r"(b0), "r"(b1));
}

__global__ __launch_bounds__(256) void k_gemm_tf32(
    const float* __restrict__ A, const float* __restrict__ B,
    const float* __restrict__ bias, float* __restrict__ C,
    int M, int K, int Nc)
{
    __shared__ unsigned As[16 * GP];
    __shared__ unsigned Bs[16 * GP];

    const int tid  = threadIdx.x;
    const int lane = tid & 31;
    const int warp = tid >> 5;
    const int wm   = warp & 1;      // 0..1 -> warp M origin wm*64
    const int wn   = warp >> 1;     // 0..3 -> warp N origin wn*32
    const int g    = lane >> 2;     // 0..7
    const int tig  = lane & 3;      // 0..3
    const int rowBase = blockIdx.y * 128;
    const int colBase = blockIdx.x * 128;

    // A gmem load: row = tid>>1 (0..127), k half = (tid&1)*8
    const int aRow = tid >> 1;
    const int aK   = (tid & 1) * 8;
    // B gmem load: row = tid>>5 (0..7, +8), col = (tid&31)*4
    const int bRow = tid >> 5;
    const int bCol = (tid & 31) * 4;

    float4 ra0, ra1, rb0, rb1;

    float acc[4][4][4];
#pragma unroll
    for (int mt = 0; mt < 4; mt++)
#pragma unroll
        for (int nt = 0; nt < 4; nt++)
#pragma unroll
            for (int q = 0; q < 4; q++) acc[mt][nt][q] = 0.0f;

#define LD_A(k0)                                                            \
    {                                                                       \
        int r = rowBase + aRow;                                             \
        if (r < M) {                                                        \
            const float* p = A + (size_t)r * K + (k0) + aK;                 \
            ra0 = *(const float4*)p;                                        \
            ra1 = *(const float4*)(p + 4);                                  \
        } else {                                                            \
            ra0 = make_float4(0.f, 0.f, 0.f, 0.f);                          \
            ra1 = make_float4(0.f, 0.f, 0.f, 0.f);                          \
        }                                                                   \
    }
#define LD_B(k0)                                                            \
    {                                                                       \
        const float* p = B + (size_t)((k0) + bRow) * Nc + colBase + bCol;   \
        rb0 = *(const float4*)p;                                            \
        rb1 = *(const float4*)(p + (size_t)8 * Nc);                         \
    }
#define ST_AB()                                                             \
    {                                                                       \
        As[(aK + 0) * GP + aRow] = f2t(ra0.x);                              \
        As[(aK + 1) * GP + aRow] = f2t(ra0.y);                              \
        As[(aK + 2) * GP + aRow] = f2t(ra0.z);                              \
        As[(aK + 3) * GP + aRow] = f2t(ra0.w);                              \
        As[(aK + 4) * GP + aRow] = f2t(ra1.x);                              \
        As[(aK + 5) * GP + aRow] = f2t(ra1.y);                              \
        As[(aK + 6) * GP + aRow] = f2t(ra1.z);                              \
        As[(aK + 7) * GP + aRow] = f2t(ra1.w);                              \
        uint4 v0 = make_uint4(f2t(rb0.x), f2t(rb0.y), f2t(rb0.z), f2t(rb0.w)); \
        uint4 v1 = make_uint4(f2t(rb1.x), f2t(rb1.y), f2t(rb1.z), f2t(rb1.w)); \
        *(uint4*)&Bs[bRow * GP + bCol]       = v0;                          \
        *(uint4*)&Bs[(bRow + 8) * GP + bCol] = v1;                          \
    }

#define COMPUTE()                                                           \
    {                                                                       \
        _Pragma("unroll")                                                   \
        for (int ks = 0; ks < 16; ks += 8) {                                \
            unsigned af[4][4], bf[4][2];                                    \
            _Pragma("unroll")                                               \
            for (int mt = 0; mt < 4; mt++) {                                \
                int m0 = wm * 64 + mt * 16;                                 \
                af[mt][0] = As[(ks + tig) * GP + m0 + g];                   \
                af[mt][1] = As[(ks + tig) * GP + m0 + g + 8];               \
                af[mt][2] = As[(ks + tig + 4) * GP + m0 + g];               \
                af[mt][3] = As[(ks + tig + 4) * GP + m0 + g + 8];           \
            }                                                               \
            _Pragma("unroll")                                               \
            for (int nt = 0; nt < 4; nt++) {                                \
                int n0 = wn * 32 + nt * 8;                                  \
                bf[nt][0] = Bs[(ks + tig) * GP + n0 + g];                   \
                bf[nt][1] = Bs[(ks + tig + 4) * GP + n0 + g];               \
            }                                                               \
            _Pragma("unroll")                                               \
            for (int mt = 0; mt < 4; mt++)                                  \
                _Pragma("unroll")                                           \
                for (int nt = 0; nt < 4; nt++)                              \
                    mma_tf32(acc[mt][nt][0], acc[mt][nt][1],                \
                             acc[mt][nt][2], acc[mt][nt][3],                \
                             af[mt][0], af[mt][1], af[mt][2], af[mt][3],    \
                             bf[nt][0], bf[nt][1]);                         \
        }                                                                   \
    }

    LD_A(0); LD_B(0);
    ST_AB();
    __syncthreads();

    const int nIter = K >> 4;
    for (int it = 1; it < nIter; it++) {
        LD_A(it * 16); LD_B(it * 16);
        COMPUTE();
        __syncthreads();
        ST_AB();
        __syncthreads();
    }
    COMPUTE();

    // epilogue: bias + relu, float2 stores
#pragma unroll
    for (int mt = 0; mt < 4; mt++) {
        int r0 = rowBase + wm * 64 + mt * 16 + g;
        int r1 = r0 + 8;
#pragma unroll
        for (int nt = 0; nt < 4; nt++) {
            int cidx = colBase + wn * 32 + nt * 8 + tig * 2;
            float bx = bias[cidx], by = bias[cidx + 1];
            if (r0 < M) {
                float2 v;
                v.x = fmaxf(acc[mt][nt][0] + bx, 0.0f);
                v.y = fmaxf(acc[mt][nt][1] + by, 0.0f);
                *(float2*)(C + (size_t)r0 * Nc + cidx) = v;
            }
            if (r1 < M) {
                float2 v;
                v.x = fmaxf(acc[mt][nt][2] + bx, 0.0f);
                v.y = fmaxf(acc[mt][nt][3] + by, 0.0f);
                *(float2*)(C + (size_t)r1 * Nc + cidx) = v;
            }
        }
    }
#undef LD_A
#undef LD_B
#undef ST_AB
#undef COMPUTE
}

// ----------------------------------------------------------------------------
// Pooling: per-feature sum and max (h >= 0 after relu -> int atomicMax valid)
// ----------------------------------------------------------------------------
#define POOL_ROWS 256
__global__ void k_pool(const float* __restrict__ h) {
    int j = threadIdx.x;
    int r0 = blockIdx.x * POOL_ROWS;
    int r1 = r0 + POOL_ROWS; if (r1 > NN) r1 = NN;
    float s = 0.0f, m = 0.0f;
    for (int r = r0; r < r1; r++) {
        float v = h[(size_t)r * HH + j];
        s += v;
        m = fmaxf(m, v);
    }
    atomicAdd(&g_psum[j], s);
    atomicMax((int*)&g_pmax[j], __float_as_int(m));
}

// ----------------------------------------------------------------------------
// Head
// ----------------------------------------------------------------------------
__global__ void k_final(const float* __restrict__ Wlin, const float* __restrict__ blin,
                        float* __restrict__ out) {
    int w = threadIdx.x >> 5;
    int lane = threadIdx.x & 31;
    if (w >= AA) return;
    const float invN = 1.0f / (float)NN;
    float acc = 0.0f;
    for (int j = lane; j < HH; j += 32) {
        float s = g_psum[j];
        float m = g_pmax[j];
        acc += s * invN * Wlin[(size_t)j * AA + w]
             + m        * Wlin[(size_t)(HH + j) * AA + w]
             + s        * Wlin[(size_t)(2 * HH + j) * AA + w];
    }
#pragma unroll
    for (int o = 16; o > 0; o >>= 1) acc += __shfl_down_sync(0xffffffffu, acc, o);
    if (lane == 0) out[w] = blin[w] + acc;
}

// ----------------------------------------------------------------------------
// Launch
// ----------------------------------------------------------------------------
extern "C" void kernel_launch(void* const* d_in, const int* in_sizes, int n_in,
                              void* d_out, int out_size) {
    const float* x    = (const float*)d_in[0];
    const int*   ei   = (const int*)d_in[1];   // int64 ref -> int32 in harness
    const float* W1   = (const float*)d_in[2];
    const float* b1   = (const float*)d_in[3];
    const float* W2   = (const float*)d_in[4];
    const float* b2   = (const float*)d_in[5];
    const float* Wlin = (const float*)d_in[6];
    const float* blin = (const float*)d_in[7];
    float*       out  = (float*)d_out;

    const int* erow = ei;        // edge_index[0] = message sources
    const int* ecol = ei + EE;   // edge_index[1] = aggregation targets

    float* buf0; cudaGetSymbolAddress((void**)&buf0, g_buf0);
    float* buf1; cudaGetSymbolAddress((void**)&buf1, g_buf1);
    void *cntp, *psp, *pmp;
    cudaGetSymbolAddress(&cntp, g_cnt);
    cudaGetSymbolAddress(&psp, g_psum);
    cudaGetSymbolAddress(&pmp, g_pmax);

    cudaMemsetAsync(cntp, 0, NN * sizeof(int));
    cudaMemsetAsync(psp, 0, HH * sizeof(float));
    cudaMemsetAsync(pmp, 0, HH * sizeof(float));

    // graph structure
    k_count<<<(EE + 255) / 256, 256>>>(ecol);
    k_blocksum<<<SBL, 256>>>();
    k_scanbsum<<<1, 256>>>();
    k_rowptr<<<SBL, 256>>>();
    k_fill<<<(EE + 255) / 256, 256>>>(erow, ecol);

    dim3 ggrid(HH / 128, (NN + 127) / 128);

    // layer 1: (A_hat x) @ W1 -> relu
    k_agg<<<NN, F_IN>>>(x, buf0);
    k_gemm_tf32<<<ggrid, 256>>>(buf0, W1, b1, buf1, NN, F_IN, HH);

    // layer 2: (A_hat h1) @ W2 -> relu
    k_agg<<<NN, HH>>>(buf1, buf0);
    k_gemm_tf32<<<ggrid, 256>>>(buf0, W2, b2, buf1, NN, HH, HH);

    // pooling + head
    k_pool<<<(NN + POOL_ROWS - 1) / POOL_ROWS, HH>>>(buf1);
    k_final<<<1, 160>>>(Wlin, blin, out);
}

// round 4
// speedup vs baseline: 2.4907x; 1.4812x over previous
#include <cuda_runtime.h>
#include <cuda_bf16.h>
#include <cstdint>

#define NN 50000
#define EE 800000
#define F_IN 128
#define HH 256
#define AA 5

// ----------------------------------------------------------------------------
// Scratch
// ----------------------------------------------------------------------------
__device__ __align__(16) float g_buf0[(size_t)NN * HH];   // agg output (tf32-rounded fp32)
__device__ __align__(16) float g_buf1[(size_t)NN * HH];   // h2 fp32
__device__ __align__(16) __nv_bfloat16 g_xb[(size_t)NN * F_IN];  // x in bf16
__device__ __align__(16) __nv_bfloat16 g_hb[(size_t)NN * HH];    // h1 in bf16
__device__ __align__(16) float g_w1r[F_IN * HH];          // tf32-rounded weights
__device__ __align__(16) float g_w2r[HH * HH];
__device__ int   g_cnt[NN];
__device__ int   g_rowptr[NN + 1];
__device__ int   g_cursor[NN];
__device__ int   g_csr[EE];
__device__ float g_dinv[NN];
__device__ float g_psum[HH];
__device__ float g_pmax[HH];
__device__ int   g_bsum[256];
__device__ int   g_boff[256];

#define SCH 200
#define SBL 250

__device__ __forceinline__ float tf32r(float f) {
    unsigned u;
    asm("cvt.rna.tf32.f32 %0, %1;" : "=r"(u) : "f"(f));
    return __uint_as_float(u);
}

// ----------------------------------------------------------------------------
// Graph build
// ----------------------------------------------------------------------------
__global__ void k_count(const int* __restrict__ col) {
    int e = blockIdx.x * blockDim.x + threadIdx.x;
    if (e < EE) atomicAdd(&g_cnt[col[e]], 1);
}

__global__ void k_blocksum() {
    __shared__ int s[256];
    int t = threadIdx.x, b = blockIdx.x;
    int i = b * SCH + t;
    s[t] = (t < SCH && i < NN) ? g_cnt[i] : 0;
    __syncthreads();
    for (int o = 128; o > 0; o >>= 1) {
        if (t < o) s[t] += s[t + o];
        __syncthreads();
    }
    if (t == 0) g_bsum[b] = s[0];
}

__global__ void k_scanbsum() {
    __shared__ int s[256];
    int t = threadIdx.x;
    s[t] = (t < SBL) ? g_bsum[t] : 0;
    __syncthreads();
    for (int o = 1; o < 256; o <<= 1) {
        int v = (t >= o) ? s[t - o] : 0;
        __syncthreads();
        s[t] += v;
        __syncthreads();
    }
    g_boff[t] = (t == 0) ? 0 : s[t - 1];
    if (t == 0) g_rowptr[NN] = EE;
}

__global__ void k_rowptr() {
    __shared__ int s[256];
    int t = threadIdx.x, b = blockIdx.x;
    int i = b * SCH + t;
    int c = (t < SCH && i < NN) ? g_cnt[i] : 0;
    s[t] = c;
    __syncthreads();
    for (int o = 1; o < 256; o <<= 1) {
        int v = (t >= o) ? s[t - o] : 0;
        __syncthreads();
        s[t] += v;
        __syncthreads();
    }
    if (t < SCH && i < NN) {
        int excl = g_boff[b] + s[t] - c;
        g_rowptr[i] = excl;
        g_cursor[i] = excl;
        g_dinv[i]   = rsqrtf((float)c + 1.0f);
    }
}

__global__ void k_fill(const int* __restrict__ row, const int* __restrict__ col) {
    int e = blockIdx.x * blockDim.x + threadIdx.x;
    if (e < EE) {
        int c = col[e];
        int p = atomicAdd(&g_cursor[c], 1);
        g_csr[p] = row[e];
    }
}

// ----------------------------------------------------------------------------
// Casts / weight rounding
// ----------------------------------------------------------------------------
__global__ void k_xcast(const float* __restrict__ x) {
    int i = blockIdx.x * blockDim.x + threadIdx.x;       // one per 4 floats
    const int n4 = NN * F_IN / 4;
    if (i >= n4) return;
    float4 v = ((const float4*)x)[i];
    __nv_bfloat162 a = __float22bfloat162_rn(make_float2(v.x, v.y));
    __nv_bfloat162 b = __float22bfloat162_rn(make_float2(v.z, v.w));
    uint2 p = make_uint2(*(unsigned*)&a, *(unsigned*)&b);
    ((uint2*)g_xb)[i] = p;
}

__global__ void k_round(const float* __restrict__ src, float* __restrict__ dst, int n) {
    int i = blockIdx.x * blockDim.x + threadIdx.x;
    if (i < n) dst[i] = tf32r(src[i]);
}

// ----------------------------------------------------------------------------
// Aggregation (bf16 input, fp32 accumulate, tf32-rounded fp32 output)
// warp per node
// ----------------------------------------------------------------------------
__global__ void k_agg_b256(const __nv_bfloat16* __restrict__ X, float* __restrict__ out) {
    int w = (blockIdx.x * blockDim.x + threadIdx.x) >> 5;
    int lane = threadIdx.x & 31;
    if (w >= NN) return;
    const uint4* Xv = (const uint4*)X;   // 32 uint4 per 256-feature row
    float dc = g_dinv[w];
    float acc[8];
    {
        uint4 u = __ldg(&Xv[(size_t)w * 32 + lane]);
        float2 f0 = __bfloat1622float2(*(__nv_bfloat162*)&u.x);
        float2 f1 = __bfloat1622float2(*(__nv_bfloat162*)&u.y);
        float2 f2 = __bfloat1622float2(*(__nv_bfloat162*)&u.z);
        float2 f3 = __bfloat1622float2(*(__nv_bfloat162*)&u.w);
        acc[0] = dc * f0.x; acc[1] = dc * f0.y; acc[2] = dc * f1.x; acc[3] = dc * f1.y;
        acc[4] = dc * f2.x; acc[5] = dc * f2.y; acc[6] = dc * f3.x; acc[7] = dc * f3.y;
    }
    int beg = g_rowptr[w], end = g_rowptr[w + 1];
    for (int e0 = beg; e0 < end; e0 += 32) {
        int m = end - e0; if (m > 32) m = 32;
        int r = 0; float dr = 0.0f;
        if (lane < m) { r = g_csr[e0 + lane]; dr = __ldg(&g_dinv[r]); }
        for (int i = 0; i < m; i++) {
            int   ri  = __shfl_sync(0xffffffffu, r, i);
            float dri = __shfl_sync(0xffffffffu, dr, i);
            uint4 u = __ldg(&Xv[(size_t)ri * 32 + lane]);
            float2 f0 = __bfloat1622float2(*(__nv_bfloat162*)&u.x);
            float2 f1 = __bfloat1622float2(*(__nv_bfloat162*)&u.y);
            float2 f2 = __bfloat1622float2(*(__nv_bfloat162*)&u.z);
            float2 f3 = __bfloat1622float2(*(__nv_bfloat162*)&u.w);
            acc[0] += dri * f0.x; acc[1] += dri * f0.y;
            acc[2] += dri * f1.x; acc[3] += dri * f1.y;
            acc[4] += dri * f2.x; acc[5] += dri * f2.y;
            acc[6] += dri * f3.x; acc[7] += dri * f3.y;
        }
    }
    float* op = out + (size_t)w * 256 + lane * 8;
    float4 v0 = make_float4(tf32r(dc * acc[0]), tf32r(dc * acc[1]),
                            tf32r(dc * acc[2]), tf32r(dc * acc[3]));
    float4 v1 = make_float4(tf32r(dc * acc[4]), tf32r(dc * acc[5]),
                            tf32r(dc * acc[6]), tf32r(dc * acc[7]));
    *(float4*)op = v0;
    *(float4*)(op + 4) = v1;
}

__global__ void k_agg_b128(const __nv_bfloat16* __restrict__ X, float* __restrict__ out) {
    int w = (blockIdx.x * blockDim.x + threadIdx.x) >> 5;
    int lane = threadIdx.x & 31;
    if (w >= NN) return;
    const uint2* Xv = (const uint2*)X;   // 32 uint2 per 128-feature row
    float dc = g_dinv[w];
    float acc[4];
    {
        uint2 u = __ldg(&Xv[(size_t)w * 32 + lane]);
        float2 f0 = __bfloat1622float2(*(__nv_bfloat162*)&u.x);
        float2 f1 = __bfloat1622float2(*(__nv_bfloat162*)&u.y);
        acc[0] = dc * f0.x; acc[1] = dc * f0.y; acc[2] = dc * f1.x; acc[3] = dc * f1.y;
    }
    int beg = g_rowptr[w], end = g_rowptr[w + 1];
    for (int e0 = beg; e0 < end; e0 += 32) {
        int m = end - e0; if (m > 32) m = 32;
        int r = 0; float dr = 0.0f;
        if (lane < m) { r = g_csr[e0 + lane]; dr = __ldg(&g_dinv[r]); }
        for (int i = 0; i < m; i++) {
            int   ri  = __shfl_sync(0xffffffffu, r, i);
            float dri = __shfl_sync(0xffffffffu, dr, i);
            uint2 u = __ldg(&Xv[(size_t)ri * 32 + lane]);
            float2 f0 = __bfloat1622float2(*(__nv_bfloat162*)&u.x);
            float2 f1 = __bfloat1622float2(*(__nv_bfloat162*)&u.y);
            acc[0] += dri * f0.x; acc[1] += dri * f0.y;
            acc[2] += dri * f1.x; acc[3] += dri * f1.y;
        }
    }
    float4 v = make_float4(tf32r(dc * acc[0]), tf32r(dc * acc[1]),
                           tf32r(dc * acc[2]), tf32r(dc * acc[3]));
    *(float4*)(out + (size_t)w * 128 + lane * 4) = v;
}

// ----------------------------------------------------------------------------
// tf32 GEMM with cp.async 2-stage pipeline.
// C = relu(A@B + bias). A,B already tf32-rounded fp32. 128x128x16 tiles,
// 8 warps (warp tile 64x32), mma.m16n8k8.tf32.
// As [m][k] pitch 20, Bs [k][n] pitch 136 (both conflict-free).
// ----------------------------------------------------------------------------
#define AP 20
#define BP 136

__device__ __forceinline__ void cpa16(uint32_t dst, const void* src, int sz) {
    asm volatile("cp.async.cg.shared.global [%0], [%1], 16, %2;\n"
                 :: "r"(dst), "l"(src), "r"(sz));
}

__device__ __forceinline__ void mma_tf32(float& c0, float& c1, float& c2, float& c3,
                                         unsigned a0, unsigned a1, unsigned a2, unsigned a3,
                                         unsigned b0, unsigned b1) {
    asm volatile(
        "mma.sync.aligned.m16n8k8.row.col.f32.tf32.tf32.f32 "
        "{%0,%1,%2,%3}, {%4,%5,%6,%7}, {%8,%9}, {%0,%1,%2,%3};"
        : "+f"(c0), "+f"(c1), "+f"(c2), "+f"(c3)
        : "r"(a0), "r"(a1), "r"(a2), "r"(a3), "r"(b0), "r"(b1));
}

template <bool OUT_BF16>
__global__ __launch_bounds__(256) void k_gemm(
    const float* __restrict__ A, const float* __restrict__ B,
    const float* __restrict__ bias, void* __restrict__ Cout,
    int M, int K, int Nc)
{
    __shared__ __align__(16) float As[2][128 * AP];
    __shared__ __align__(16) float Bs[2][16 * BP];

    const int tid  = threadIdx.x;
    const int lane = tid & 31;
    const int warp = tid >> 5;
    const int wm   = warp & 1;
    const int wn   = warp >> 1;
    const int g    = lane >> 2;
    const int tig  = lane & 3;
    const int rowBase = blockIdx.y * 128;
    const int colBase = blockIdx.x * 128;

    // load mapping: A chunks c = tid*2+{0,1}: m=c>>2, kc=(c&3)*4
    const int ac0 = tid * 2, ac1 = tid * 2 + 1;
    const int am0 = ac0 >> 2, ak0 = (ac0 & 3) * 4;
    const int am1 = ac1 >> 2, ak1 = (ac1 & 3) * 4;
    // B chunks: row=c>>5, col=(c&31)*4
    const int br0 = ac0 >> 5, bc0 = (ac0 & 31) * 4;
    const int br1 = ac1 >> 5, bc1 = (ac1 & 31) * 4;

    uint32_t asm0 = (uint32_t)__cvta_generic_to_shared(&As[0][0]);
    uint32_t asm1 = (uint32_t)__cvta_generic_to_shared(&As[1][0]);
    uint32_t bsm0 = (uint32_t)__cvta_generic_to_shared(&Bs[0][0]);
    uint32_t bsm1 = (uint32_t)__cvta_generic_to_shared(&Bs[1][0]);

    float acc[4][4][4];
#pragma unroll
    for (int mt = 0; mt < 4; mt++)
#pragma unroll
        for (int nt = 0; nt < 4; nt++)
#pragma unroll
            for (int q = 0; q < 4; q++) acc[mt][nt][q] = 0.0f;

#define ISSUE(stage, k0)                                                        \
    {                                                                           \
        uint32_t ad = (stage) ? asm1 : asm0;                                    \
        uint32_t bd = (stage) ? bsm1 : bsm0;                                    \
        int r0 = rowBase + am0, r1 = rowBase + am1;                             \
        const float* s0 = A + (size_t)((r0 < M) ? r0 : 0) * K + (k0) + ak0;     \
        const float* s1 = A + (size_t)((r1 < M) ? r1 : 0) * K + (k0) + ak1;     \
        cpa16(ad + (am0 * AP + ak0) * 4, s0, (r0 < M) ? 16 : 0);                \
        cpa16(ad + (am1 * AP + ak1) * 4, s1, (r1 < M) ? 16 : 0);                \
        cpa16(bd + (br0 * BP + bc0) * 4,                                        \
              B + (size_t)((k0) + br0) * Nc + colBase + bc0, 16);               \
        cpa16(bd + (br1 * BP + bc1) * 4,                                        \
              B + (size_t)((k0) + br1) * Nc + colBase + bc1, 16);               \
        asm volatile("cp.async.commit_group;\n" ::: "memory");                  \
    }

#define COMPUTE(stage)                                                          \
    {                                                                           \
        const float* Ap = As[stage];                                            \
        const float* Bp = Bs[stage];                                            \
        _Pragma("unroll")                                                       \
        for (int ks = 0; ks < 16; ks += 8) {                                    \
            unsigned af[4][4], bf[4][2];                                        \
            _Pragma("unroll")                                                   \
            for (int mt = 0; mt < 4; mt++) {                                    \
                int m0 = wm * 64 + mt * 16;                                     \
                af[mt][0] = __float_as_uint(Ap[(m0 + g) * AP + ks + tig]);      \
                af[mt][1] = __float_as_uint(Ap[(m0 + g + 8) * AP + ks + tig]);  \
                af[mt][2] = __float_as_uint(Ap[(m0 + g) * AP + ks + tig + 4]);  \
                af[mt][3] = __float_as_uint(Ap[(m0 + g + 8) * AP + ks + tig + 4]); \
            }                                                                   \
            _Pragma("unroll")                                                   \
            for (int nt = 0; nt < 4; nt++) {                                    \
                int n0 = wn * 32 + nt * 8;                                      \
                bf[nt][0] = __float_as_uint(Bp[(ks + tig) * BP + n0 + g]);      \
                bf[nt][1] = __float_as_uint(Bp[(ks + tig + 4) * BP + n0 + g]);  \
            }                                                                   \
            _Pragma("unroll")                                                   \
            for (int mt = 0; mt < 4; mt++)                                      \
                _Pragma("unroll")                                               \
                for (int nt = 0; nt < 4; nt++)                                  \
                    mma_tf32(acc[mt][nt][0], acc[mt][nt][1],                    \
                             acc[mt][nt][2], acc[mt][nt][3],                    \
                             af[mt][0], af[mt][1], af[mt][2], af[mt][3],        \
                             bf[nt][0], bf[nt][1]);                             \
        }                                                                       \
    }

    const int nIter = K >> 4;
    ISSUE(0, 0);
    for (int it = 0; it < nIter; it++) {
        if (it + 1 < nIter) {
            ISSUE((it + 1) & 1, (it + 1) * 16);
            asm volatile("cp.async.wait_group 1;\n" ::: "memory");
        } else {
            asm volatile("cp.async.wait_group 0;\n" ::: "memory");
        }
        __syncthreads();
        COMPUTE(it & 1);
        __syncthreads();
    }

    // epilogue
#pragma unroll
    for (int mt = 0; mt < 4; mt++) {
        int r0 = rowBase + wm * 64 + mt * 16 + g;
        int r1 = r0 + 8;
#pragma unroll
        for (int nt = 0; nt < 4; nt++) {
            int cidx = colBase + wn * 32 + nt * 8 + tig * 2;
            float bx = bias[cidx], by = bias[cidx + 1];
            float v00 = fmaxf(acc[mt][nt][0] + bx, 0.0f);
            float v01 = fmaxf(acc[mt][nt][1] + by, 0.0f);
            float v10 = fmaxf(acc[mt][nt][2] + bx, 0.0f);
            float v11 = fmaxf(acc[mt][nt][3] + by, 0.0f);
            if (OUT_BF16) {
                __nv_bfloat16* C = (__nv_bfloat16*)Cout;
                if (r0 < M) {
                    __nv_bfloat162 p = __float22bfloat162_rn(make_float2(v00, v01));
                    *(__nv_bfloat162*)(C + (size_t)r0 * Nc + cidx) = p;
                }
                if (r1 < M) {
                    __nv_bfloat162 p = __float22bfloat162_rn(make_float2(v10, v11));
                    *(__nv_bfloat162*)(C + (size_t)r1 * Nc + cidx) = p;
                }
            } else {
                float* C = (float*)Cout;
                if (r0 < M) *(float2*)(C + (size_t)r0 * Nc + cidx) = make_float2(v00, v01);
                if (r1 < M) *(float2*)(C + (size_t)r1 * Nc + cidx) = make_float2(v10, v11);
            }
        }
    }
#undef ISSUE
#undef COMPUTE
}

// ----------------------------------------------------------------------------
// Pooling + head
// ----------------------------------------------------------------------------
#define POOL_ROWS 256
__global__ void k_pool(const float* __restrict__ h) {
    int j = threadIdx.x;
    int r0 = blockIdx.x * POOL_ROWS;
    int r1 = r0 + POOL_ROWS; if (r1 > NN) r1 = NN;
    float s = 0.0f, m = 0.0f;
    for (int r = r0; r < r1; r++) {
        float v = h[(size_t)r * HH + j];
        s += v;
        m = fmaxf(m, v);
    }
    atomicAdd(&g_psum[j], s);
    atomicMax((int*)&g_pmax[j], __float_as_int(m));
}

__global__ void k_final(const float* __restrict__ Wlin, const float* __restrict__ blin,
                        float* __restrict__ out) {
    int w = threadIdx.x >> 5;
    int lane = threadIdx.x & 31;
    if (w >= AA) return;
    const float invN = 1.0f / (float)NN;
    float acc = 0.0f;
    for (int j = lane; j < HH; j += 32) {
        float s = g_psum[j];
        float m = g_pmax[j];
        acc += s * invN * Wlin[(size_t)j * AA + w]
             + m        * Wlin[(size_t)(HH + j) * AA + w]
             + s        * Wlin[(size_t)(2 * HH + j) * AA + w];
    }
#pragma unroll
    for (int o = 16; o > 0; o >>= 1) acc += __shfl_down_sync(0xffffffffu, acc, o);
    if (lane == 0) out[w] = blin[w] + acc;
}

// ----------------------------------------------------------------------------
// Launch
// ----------------------------------------------------------------------------
extern "C" void kernel_launch(void* const* d_in, const int* in_sizes, int n_in,
                              void* d_out, int out_size) {
    const float* x    = (const float*)d_in[0];
    const int*   ei   = (const int*)d_in[1];
    const float* W1   = (const float*)d_in[2];
    const float* b1   = (const float*)d_in[3];
    const float* W2   = (const float*)d_in[4];
    const float* b2   = (const float*)d_in[5];
    const float* Wlin = (const float*)d_in[6];
    const float* blin = (const float*)d_in[7];
    float*       out  = (float*)d_out;

    const int* erow = ei;
    const int* ecol = ei + EE;

    float* buf0; cudaGetSymbolAddress((void**)&buf0, g_buf0);
    float* buf1; cudaGetSymbolAddress((void**)&buf1, g_buf1);
    __nv_bfloat16* xb; cudaGetSymbolAddress((void**)&xb, g_xb);
    __nv_bfloat16* hb; cudaGetSymbolAddress((void**)&hb, g_hb);
    float* w1r; cudaGetSymbolAddress((void**)&w1r, g_w1r);
    float* w2r; cudaGetSymbolAddress((void**)&w2r, g_w2r);
    void *cntp, *psp, *pmp;
    cudaGetSymbolAddress(&cntp, g_cnt);
    cudaGetSymbolAddress(&psp, g_psum);
    cudaGetSymbolAddress(&pmp, g_pmax);

    cudaMemsetAsync(cntp, 0, NN * sizeof(int));
    cudaMemsetAsync(psp, 0, HH * sizeof(float));
    cudaMemsetAsync(pmp, 0, HH * sizeof(float));

    // graph structure
    k_count<<<(EE + 255) / 256, 256>>>(ecol);
    k_blocksum<<<SBL, 256>>>();
    k_scanbsum<<<1, 256>>>();
    k_rowptr<<<SBL, 256>>>();
    k_fill<<<(EE + 255) / 256, 256>>>(erow, ecol);

    // casts / weight rounding (independent of graph build)
    k_xcast<<<(NN * F_IN / 4 + 255) / 256, 256>>>(x);
    k_round<<<(F_IN * HH + 255) / 256, 256>>>(W1, w1r, F_IN * HH);
    k_round<<<(HH * HH + 255) / 256, 256>>>(W2, w2r, HH * HH);

    dim3 ggrid(HH / 128, (NN + 127) / 128);
    const int aggBlocks = (NN + 7) / 8;  // 8 warps per block

    // layer 1
    k_agg_b128<<<aggBlocks, 256>>>(xb, buf0);
    k_gemm<true><<<ggrid, 256>>>(buf0, w1r, b1, hb, NN, F_IN, HH);

    // layer 2
    k_agg_b256<<<aggBlocks, 256>>>(hb, buf0);
    k_gemm<false><<<ggrid, 256>>>(buf0, w2r, b2, buf1, NN, HH, HH);

    // pooling + head
    k_pool<<<(NN + POOL_ROWS - 1) / POOL_ROWS, HH>>>(buf1);
    k_final<<<1, 160>>>(Wlin, blin, out);
}

// round 7
// speedup vs baseline: 3.2748x; 1.3148x over previous
#include <cuda_runtime.h>
#include <cuda_fp16.h>
#include <cstdint>

#define NN 50000
#define EE 800000
#define F_IN 128
#define HH 256
#define AA 5

// ----------------------------------------------------------------------------
// Scratch
// ----------------------------------------------------------------------------
__device__ __align__(16) __half g_xb[(size_t)NN * F_IN];   // x fp16
__device__ __align__(16) __half g_a1[(size_t)NN * F_IN];   // agg1 out fp16
__device__ __align__(16) __half g_hb[(size_t)NN * HH];     // h1 fp16
__device__ __align__(16) __half g_a2[(size_t)NN * HH];     // agg2 out fp16
__device__ __align__(16) __half g_w1t[HH * F_IN];          // W1^T fp16 [N][K]
__device__ __align__(16) __half g_w2t[HH * HH];            // W2^T fp16 [N][K]
__device__ int   g_cnt[NN];
__device__ int   g_rowptr[NN + 1];
__device__ int   g_cursor[NN];
__device__ int   g_csr[EE];
__device__ float g_dinv[NN];
__device__ float g_psum[HH];
__device__ float g_pmax[HH];
__device__ int   g_bsum[256];
__device__ int   g_boff[256];

#define SCH 200
#define SBL 250

// ----------------------------------------------------------------------------
// Graph build
// ----------------------------------------------------------------------------
__global__ void k_count(const int* __restrict__ col) {
    int e = blockIdx.x * blockDim.x + threadIdx.x;
    if (e < EE) atomicAdd(&g_cnt[col[e]], 1);
}

__global__ void k_blocksum() {
    __shared__ int s[256];
    int t = threadIdx.x, b = blockIdx.x;
    int i = b * SCH + t;
    s[t] = (t < SCH && i < NN) ? g_cnt[i] : 0;
    __syncthreads();
    for (int o = 128; o > 0; o >>= 1) {
        if (t < o) s[t] += s[t + o];
        __syncthreads();
    }
    if (t == 0) g_bsum[b] = s[0];
}

__global__ void k_scanbsum() {
    __shared__ int s[256];
    int t = threadIdx.x;
    s[t] = (t < SBL) ? g_bsum[t] : 0;
    __syncthreads();
    for (int o = 1; o < 256; o <<= 1) {
        int v = (t >= o) ? s[t - o] : 0;
        __syncthreads();
        s[t] += v;
        __syncthreads();
    }
    g_boff[t] = (t == 0) ? 0 : s[t - 1];
    if (t == 0) g_rowptr[NN] = EE;
}

__global__ void k_rowptr() {
    __shared__ int s[256];
    int t = threadIdx.x, b = blockIdx.x;
    int i = b * SCH + t;
    int c = (t < SCH && i < NN) ? g_cnt[i] : 0;
    s[t] = c;
    __syncthreads();
    for (int o = 1; o < 256; o <<= 1) {
        int v = (t >= o) ? s[t - o] : 0;
        __syncthreads();
        s[t] += v;
        __syncthreads();
    }
    if (t < SCH && i < NN) {
        int excl = g_boff[b] + s[t] - c;
        g_rowptr[i] = excl;
        g_cursor[i] = excl;
        g_dinv[i]   = rsqrtf((float)c + 1.0f);
    }
}

__global__ void k_fill(const int* __restrict__ row, const int* __restrict__ col) {
    int e = blockIdx.x * blockDim.x + threadIdx.x;
    if (e < EE) {
        int c = col[e];
        int p = atomicAdd(&g_cursor[c], 1);
        g_csr[p] = row[e];
    }
}

// ----------------------------------------------------------------------------
// Casts: x -> fp16 ; W (K x N fp32) -> W^T (N x K fp16)
// ----------------------------------------------------------------------------
__global__ void k_xcast(const float* __restrict__ x) {
    int i = blockIdx.x * blockDim.x + threadIdx.x;
    const int n4 = NN * F_IN / 4;
    if (i >= n4) return;
    float4 v = ((const float4*)x)[i];
    __half2 a = __float22half2_rn(make_float2(v.x, v.y));
    __half2 b = __float22half2_rn(make_float2(v.z, v.w));
    ((uint2*)g_xb)[i] = make_uint2(*(unsigned*)&a, *(unsigned*)&b);
}

__global__ void k_wt(const float* __restrict__ W, __half* __restrict__ Wt,
                     int K, int Nw) {
    int i = blockIdx.x * blockDim.x + threadIdx.x;
    if (i >= K * Nw) return;
    int n = i / K, k = i - n * K;
    Wt[i] = __float2half_rn(W[(size_t)k * Nw + n]);
}

// ----------------------------------------------------------------------------
// Aggregation (fp16 in, fp32 accumulate, fp16 out), warp per node
// ----------------------------------------------------------------------------
__global__ void k_agg_b256(const __half* __restrict__ X, __half* __restrict__ out) {
    int w = (blockIdx.x * blockDim.x + threadIdx.x) >> 5;
    int lane = threadIdx.x & 31;
    if (w >= NN) return;
    const uint4* Xv = (const uint4*)X;
    float dc = g_dinv[w];
    float acc[8];
    {
        uint4 u = __ldg(&Xv[(size_t)w * 32 + lane]);
        float2 f0 = __half22float2(*(__half2*)&u.x);
        float2 f1 = __half22float2(*(__half2*)&u.y);
        float2 f2 = __half22float2(*(__half2*)&u.z);
        float2 f3 = __half22float2(*(__half2*)&u.w);
        acc[0] = dc * f0.x; acc[1] = dc * f0.y; acc[2] = dc * f1.x; acc[3] = dc * f1.y;
        acc[4] = dc * f2.x; acc[5] = dc * f2.y; acc[6] = dc * f3.x; acc[7] = dc * f3.y;
    }
    int beg = g_rowptr[w], end = g_rowptr[w + 1];
    for (int e0 = beg; e0 < end; e0 += 32) {
        int m = end - e0; if (m > 32) m = 32;
        int r = 0; float dr = 0.0f;
        if (lane < m) { r = g_csr[e0 + lane]; dr = __ldg(&g_dinv[r]); }
        for (int i = 0; i < m; i++) {
            int   ri  = __shfl_sync(0xffffffffu, r, i);
            float dri = __shfl_sync(0xffffffffu, dr, i);
            uint4 u = __ldg(&Xv[(size_t)ri * 32 + lane]);
            float2 f0 = __half22float2(*(__half2*)&u.x);
            float2 f1 = __half22float2(*(__half2*)&u.y);
            float2 f2 = __half22float2(*(__half2*)&u.z);
            float2 f3 = __half22float2(*(__half2*)&u.w);
            acc[0] += dri * f0.x; acc[1] += dri * f0.y;
            acc[2] += dri * f1.x; acc[3] += dri * f1.y;
            acc[4] += dri * f2.x; acc[5] += dri * f2.y;
            acc[6] += dri * f3.x; acc[7] += dri * f3.y;
        }
    }
    __half2 p0 = __float22half2_rn(make_float2(dc * acc[0], dc * acc[1]));
    __half2 p1 = __float22half2_rn(make_float2(dc * acc[2], dc * acc[3]));
    __half2 p2 = __float22half2_rn(make_float2(dc * acc[4], dc * acc[5]));
    __half2 p3 = __float22half2_rn(make_float2(dc * acc[6], dc * acc[7]));
    ((uint4*)out)[(size_t)w * 32 + lane] =
        make_uint4(*(unsigned*)&p0, *(unsigned*)&p1, *(unsigned*)&p2, *(unsigned*)&p3);
}

__global__ void k_agg_b128(const __half* __restrict__ X, __half* __restrict__ out) {
    int w = (blockIdx.x * blockDim.x + threadIdx.x) >> 5;
    int lane = threadIdx.x & 31;
    if (w >= NN) return;
    const uint2* Xv = (const uint2*)X;
    float dc = g_dinv[w];
    float acc[4];
    {
        uint2 u = __ldg(&Xv[(size_t)w * 32 + lane]);
        float2 f0 = __half22float2(*(__half2*)&u.x);
        float2 f1 = __half22float2(*(__half2*)&u.y);
        acc[0] = dc * f0.x; acc[1] = dc * f0.y; acc[2] = dc * f1.x; acc[3] = dc * f1.y;
    }
    int beg = g_rowptr[w], end = g_rowptr[w + 1];
    for (int e0 = beg; e0 < end; e0 += 32) {
        int m = end - e0; if (m > 32) m = 32;
        int r = 0; float dr = 0.0f;
        if (lane < m) { r = g_csr[e0 + lane]; dr = __ldg(&g_dinv[r]); }
        for (int i = 0; i < m; i++) {
            int   ri  = __shfl_sync(0xffffffffu, r, i);
            float dri = __shfl_sync(0xffffffffu, dr, i);
            uint2 u = __ldg(&Xv[(size_t)ri * 32 + lane]);
            float2 f0 = __half22float2(*(__half2*)&u.x);
            float2 f1 = __half22float2(*(__half2*)&u.y);
            acc[0] += dri * f0.x; acc[1] += dri * f0.y;
            acc[2] += dri * f1.x; acc[3] += dri * f1.y;
        }
    }
    __half2 p0 = __float22half2_rn(make_float2(dc * acc[0], dc * acc[1]));
    __half2 p1 = __float22half2_rn(make_float2(dc * acc[2], dc * acc[3]));
    ((uint2*)out)[(size_t)w * 32 + lane] = make_uint2(*(unsigned*)&p0, *(unsigned*)&p1);
}

// ----------------------------------------------------------------------------
// fp16 tensor-core GEMM: 128x128 block, k-chunk 32, 2-stage cp.async,
// mma.m16n8k16.f16 (fp32 accum), 8 warps (warp tile 64x32).
// A [M][K] fp16 row-major; Bt [N][K] fp16 row-major (pre-transposed weights).
// MODE 0: C = relu(A@B + bias) written fp16.
// MODE 1: no C; per-column sum/max of relu(A@B + bias) accumulated into
//         g_psum / g_pmax (global pooling fused).
// smem pitch 40 halves -> frag loads conflict-free (banks 20g+tig mod 32).
// ----------------------------------------------------------------------------
#define SP 40

__device__ __forceinline__ void cpa16(uint32_t dst, const void* src, int sz) {
    asm volatile("cp.async.cg.shared.global [%0], [%1], 16, %2;\n"
                 :: "r"(dst), "l"(src), "r"(sz));
}

__device__ __forceinline__ void mma_fp16(float& c0, float& c1, float& c2, float& c3,
                                         unsigned a0, unsigned a1, unsigned a2, unsigned a3,
                                         unsigned b0, unsigned b1) {
    asm volatile(
        "mma.sync.aligned.m16n8k16.row.col.f32.f16.f16.f32 "
        "{%0,%1,%2,%3}, {%4,%5,%6,%7}, {%8,%9}, {%0,%1,%2,%3};"
        : "+f"(c0), "+f"(c1), "+f"(c2), "+f"(c3)
        : "r"(a0), "r"(a1), "r"(a2), "r"(a3), "r"(b0), "r"(b1));
}

template <int MODE>
__global__ __launch_bounds__(256) void k_gemm_fp16(
    const __half* __restrict__ A, const __half* __restrict__ Bt,
    const float* __restrict__ bias, __half* __restrict__ C,
    int M, int K, int Nc)
{
    __shared__ __align__(16) __half As[2][128 * SP];
    __shared__ __align__(16) __half Bs[2][128 * SP];

    const int tid  = threadIdx.x;
    const int lane = tid & 31;
    const int warp = tid >> 5;
    const int wm   = warp & 1;
    const int wn   = warp >> 1;
    const int g    = lane >> 2;
    const int tig  = lane & 3;
    const int rowBase = blockIdx.y * 128;
    const int colBase = blockIdx.x * 128;

    // cp.async mapping: thread t -> tile row t>>1, 32 bytes at quarter 2*(t&1)
    const int lrow = tid >> 1;
    const int lq   = (tid & 1) * 2;            // quarters lq, lq+1 (each 8 halves)
    const int dA0  = (lrow * SP + lq * 8) * 2; // byte offsets in stage
    const int dA1  = dA0 + 16;

    uint32_t as0 = (uint32_t)__cvta_generic_to_shared(&As[0][0]);
    uint32_t as1 = (uint32_t)__cvta_generic_to_shared(&As[1][0]);
    uint32_t bs0 = (uint32_t)__cvta_generic_to_shared(&Bs[0][0]);
    uint32_t bs1 = (uint32_t)__cvta_generic_to_shared(&Bs[1][0]);

    const int rA = rowBase + lrow;
    const int okA = (rA < M) ? 16 : 0;
    const __half* srcA = A + (size_t)((rA < M) ? rA : 0) * K + lq * 8;
    const __half* srcB = Bt + (size_t)(colBase + lrow) * K + lq * 8;

    float acc[4][4][4];
#pragma unroll
    for (int mt = 0; mt < 4; mt++)
#pragma unroll
        for (int nt = 0; nt < 4; nt++)
#pragma unroll
            for (int q = 0; q < 4; q++) acc[mt][nt][q] = 0.0f;

#define ISSUE(stage, k0)                                                       \
    {                                                                          \
        uint32_t ad = (stage) ? as1 : as0;                                     \
        uint32_t bd = (stage) ? bs1 : bs0;                                     \
        cpa16(ad + dA0, srcA + (k0), okA);                                     \
        cpa16(ad + dA1, srcA + (k0) + 8, okA);                                 \
        cpa16(bd + dA0, srcB + (k0), 16);                                      \
        cpa16(bd + dA1, srcB + (k0) + 8, 16);                                  \
        asm volatile("cp.async.commit_group;\n" ::: "memory");                 \
    }

#define COMPUTE(stage)                                                         \
    {                                                                          \
        const __half* Ap = As[stage];                                          \
        const __half* Bp = Bs[stage];                                          \
        _Pragma("unroll")                                                      \
        for (int ks = 0; ks < 32; ks += 16) {                                  \
            unsigned af[4][4], bf[4][2];                                       \
            _Pragma("unroll")                                                  \
            for (int mt = 0; mt < 4; mt++) {                                   \
                int m0 = wm * 64 + mt * 16;                                    \
                af[mt][0] = *(const unsigned*)&Ap[(m0 + g) * SP + ks + tig * 2];      \
                af[mt][1] = *(const unsigned*)&Ap[(m0 + g + 8) * SP + ks + tig * 2];  \
                af[mt][2] = *(const unsigned*)&Ap[(m0 + g) * SP + ks + tig * 2 + 8];  \
                af[mt][3] = *(const unsigned*)&Ap[(m0 + g + 8) * SP + ks + tig * 2 + 8]; \
            }                                                                  \
            _Pragma("unroll")                                                  \
            for (int nt = 0; nt < 4; nt++) {                                   \
                int n0 = wn * 32 + nt * 8;                                     \
                bf[nt][0] = *(const unsigned*)&Bp[(n0 + g) * SP + ks + tig * 2];      \
                bf[nt][1] = *(const unsigned*)&Bp[(n0 + g) * SP + ks + tig * 2 + 8];  \
            }                                                                  \
            _Pragma("unroll")                                                  \
            for (int mt = 0; mt < 4; mt++)                                     \
                _Pragma("unroll")                                              \
                for (int nt = 0; nt < 4; nt++)                                 \
                    mma_fp16(acc[mt][nt][0], acc[mt][nt][1],                   \
                             acc[mt][nt][2], acc[mt][nt][3],                   \
                             af[mt][0], af[mt][1], af[mt][2], af[mt][3],       \
                             bf[nt][0], bf[nt][1]);                            \
        }                                                                      \
    }

    const int nIter = K >> 5;
    ISSUE(0, 0);
    for (int it = 0; it < nIter; it++) {
        if (it + 1 < nIter) {
            ISSUE((it + 1) & 1, (it + 1) * 32);
            asm volatile("cp.async.wait_group 1;\n" ::: "memory");
        } else {
            asm volatile("cp.async.wait_group 0;\n" ::: "memory");
        }
        __syncthreads();
        COMPUTE(it & 1);
        __syncthreads();
    }

    if (MODE == 0) {
#pragma unroll
        for (int mt = 0; mt < 4; mt++) {
            int r0 = rowBase + wm * 64 + mt * 16 + g;
            int r1 = r0 + 8;
#pragma unroll
            for (int nt = 0; nt < 4; nt++) {
                int cidx = colBase + wn * 32 + nt * 8 + tig * 2;
                float bx = bias[cidx], by = bias[cidx + 1];
                if (r0 < M) {
                    __half2 p = __float22half2_rn(make_float2(
                        fmaxf(acc[mt][nt][0] + bx, 0.0f), fmaxf(acc[mt][nt][1] + by, 0.0f)));
                    *(__half2*)(C + (size_t)r0 * Nc + cidx) = p;
                }
                if (r1 < M) {
                    __half2 p = __float22half2_rn(make_float2(
                        fmaxf(acc[mt][nt][2] + bx, 0.0f), fmaxf(acc[mt][nt][3] + by, 0.0f)));
                    *(__half2*)(C + (size_t)r1 * Nc + cidx) = p;
                }
            }
        }
    } else {
        // fused global pooling: per-column sum & max over this block's rows
        float ps[4][2], pm[4][2];
#pragma unroll
        for (int nt = 0; nt < 4; nt++) { ps[nt][0] = ps[nt][1] = 0.0f; pm[nt][0] = pm[nt][1] = 0.0f; }
#pragma unroll
        for (int mt = 0; mt < 4; mt++) {
            int r0 = rowBase + wm * 64 + mt * 16 + g;
            int r1 = r0 + 8;
#pragma unroll
            for (int nt = 0; nt < 4; nt++) {
                int cidx = colBase + wn * 32 + nt * 8 + tig * 2;
                float bx = bias[cidx], by = bias[cidx + 1];
                if (r0 < M) {
                    float v0 = fmaxf(acc[mt][nt][0] + bx, 0.0f);
                    float v1 = fmaxf(acc[mt][nt][1] + by, 0.0f);
                    ps[nt][0] += v0; ps[nt][1] += v1;
                    pm[nt][0] = fmaxf(pm[nt][0], v0); pm[nt][1] = fmaxf(pm[nt][1], v1);
                }
                if (r1 < M) {
                    float v0 = fmaxf(acc[mt][nt][2] + bx, 0.0f);
                    float v1 = fmaxf(acc[mt][nt][3] + by, 0.0f);
                    ps[nt][0] += v0; ps[nt][1] += v1;
                    pm[nt][0] = fmaxf(pm[nt][0], v0); pm[nt][1] = fmaxf(pm[nt][1], v1);
                }
            }
        }
        // reduce over g (lanes xor 4,8,16 share the same columns)
#pragma unroll
        for (int o = 4; o <= 16; o <<= 1) {
#pragma unroll
            for (int nt = 0; nt < 4; nt++) {
#pragma unroll
                for (int p = 0; p < 2; p++) {
                    ps[nt][p] += __shfl_xor_sync(0xffffffffu, ps[nt][p], o);
                    pm[nt][p] = fmaxf(pm[nt][p], __shfl_xor_sync(0xffffffffu, pm[nt][p], o));
                }
            }
        }
        if (lane < 4) {
#pragma unroll
            for (int nt = 0; nt < 4; nt++) {
#pragma unroll
                for (int p = 0; p < 2; p++) {
                    int col = colBase + wn * 32 + nt * 8 + lane * 2 + p;
                    atomicAdd(&g_psum[col], ps[nt][p]);
                    atomicMax((int*)&g_pmax[col], __float_as_int(pm[nt][p]));
                }
            }
        }
    }
#undef ISSUE
#undef COMPUTE
}

// ----------------------------------------------------------------------------
// Head
// ----------------------------------------------------------------------------
__global__ void k_final(const float* __restrict__ Wlin, const float* __restrict__ blin,
                        float* __restrict__ out) {
    int w = threadIdx.x >> 5;
    int lane = threadIdx.x & 31;
    if (w >= AA) return;
    const float invN = 1.0f / (float)NN;
    float acc = 0.0f;
    for (int j = lane; j < HH; j += 32) {
        float s = g_psum[j];
        float m = g_pmax[j];
        acc += s * invN * Wlin[(size_t)j * AA + w]
             + m        * Wlin[(size_t)(HH + j) * AA + w]
             + s        * Wlin[(size_t)(2 * HH + j) * AA + w];
    }
#pragma unroll
    for (int o = 16; o > 0; o >>= 1) acc += __shfl_down_sync(0xffffffffu, acc, o);
    if (lane == 0) out[w] = blin[w] + acc;
}

// ----------------------------------------------------------------------------
// Launch
// ----------------------------------------------------------------------------
extern "C" void kernel_launch(void* const* d_in, const int* in_sizes, int n_in,
                              void* d_out, int out_size) {
    const float* x    = (const float*)d_in[0];
    const int*   ei   = (const int*)d_in[1];
    const float* W1   = (const float*)d_in[2];
    const float* b1   = (const float*)d_in[3];
    const float* W2   = (const float*)d_in[4];
    const float* b2   = (const float*)d_in[5];
    const float* Wlin = (const float*)d_in[6];
    const float* blin = (const float*)d_in[7];
    float*       out  = (float*)d_out;

    const int* erow = ei;
    const int* ecol = ei + EE;

    __half *xb, *a1, *hb, *a2, *w1t, *w2t;
    cudaGetSymbolAddress((void**)&xb, g_xb);
    cudaGetSymbolAddress((void**)&a1, g_a1);
    cudaGetSymbolAddress((void**)&hb, g_hb);
    cudaGetSymbolAddress((void**)&a2, g_a2);
    cudaGetSymbolAddress((void**)&w1t, g_w1t);
    cudaGetSymbolAddress((void**)&w2t, g_w2t);
    void *cntp, *psp, *pmp;
    cudaGetSymbolAddress(&cntp, g_cnt);
    cudaGetSymbolAddress(&psp, g_psum);
    cudaGetSymbolAddress(&pmp, g_pmax);

    cudaMemsetAsync(cntp, 0, NN * sizeof(int));
    cudaMemsetAsync(psp, 0, HH * sizeof(float));
    cudaMemsetAsync(pmp, 0, HH * sizeof(float));

    // graph structure
    k_count<<<(EE + 255) / 256, 256>>>(ecol);
    k_blocksum<<<SBL, 256>>>();
    k_scanbsum<<<1, 256>>>();
    k_rowptr<<<SBL, 256>>>();
    k_fill<<<(EE + 255) / 256, 256>>>(erow, ecol);

    // casts (independent of graph build)
    k_xcast<<<(NN * F_IN / 4 + 255) / 256, 256>>>(x);
    k_wt<<<(F_IN * HH + 255) / 256, 256>>>(W1, w1t, F_IN, HH);
    k_wt<<<(HH * HH + 255) / 256, 256>>>(W2, w2t, HH, HH);

    dim3 ggrid(HH / 128, (NN + 127) / 128);
    const int aggBlocks = (NN + 7) / 8;  // 8 warps per block

    // layer 1
    k_agg_b128<<<aggBlocks, 256>>>(xb, a1);
    k_gemm_fp16<0><<<ggrid, 256>>>(a1, w1t, b1, hb, NN, F_IN, HH);

    // layer 2 (pooling fused into GEMM epilogue; no h2 tensor)
    k_agg_b256<<<aggBlocks, 256>>>(hb, a2);
    k_gemm_fp16<1><<<ggrid, 256>>>(a2, w2t, b2, nullptr, NN, HH, HH);

    // head
    k_final<<<1, 160>>>(Wlin, blin, out);
}

// round 9
// speedup vs baseline: 3.5734x; 1.0912x over previous
#include <cuda_runtime.h>
#include <cuda_fp16.h>
#include <cstdint>

#define NN 50000
#define EE 800000
#define F_IN 128
#define HH 256
#define AA 5

// ----------------------------------------------------------------------------
// Scratch
// ----------------------------------------------------------------------------
__device__ __align__(16) __half   g_xb[(size_t)NN * F_IN];  // x fp16
__device__ __align__(16) __half   g_a1[(size_t)NN * F_IN];  // agg1 out fp16
__device__ __align__(16) uint8_t  g_h8[(size_t)NN * HH];    // h1 fp8 e4m3
__device__ __align__(16) __half   g_a2[(size_t)NN * HH];    // agg2 out fp16
__device__ __align__(16) __half   g_w1t[HH * F_IN];         // W1^T fp16 [N][K]
__device__ __align__(16) __half   g_w2t[HH * HH];           // W2^T fp16 [N][K]
__device__ int   g_cnt[NN];
__device__ int   g_rowptr[NN + 1];
__device__ int   g_cursor[NN];
__device__ int   g_csr[EE];
__device__ float g_dinv[NN];
__device__ float g_psum[HH];
__device__ float g_pmax[HH];
__device__ int   g_bsum[256];
__device__ int   g_boff[256];

#define SCH 200
#define SBL 250

// fp8 e4m3 helpers
__device__ __forceinline__ unsigned short f2e4m3x2(float hi, float lo) {
    unsigned short r;
    asm("cvt.rn.satfinite.e4m3x2.f32 %0, %1, %2;" : "=h"(r) : "f"(hi), "f"(lo));
    return r;
}
__device__ __forceinline__ float2 e4m3x2_2f(unsigned short v) {
    unsigned h2;
    asm("cvt.rn.f16x2.e4m3x2 %0, %1;" : "=r"(h2) : "h"(v));
    return __half22float2(*(__half2*)&h2);
}

// ----------------------------------------------------------------------------
// prep: zero cnt/psum/pmax, cast x -> fp16, transpose W1/W2 -> fp16 [N][K]
// grid covers NN*F_IN/4 = 1.6M threads (superset of all tasks)
// ----------------------------------------------------------------------------
__global__ void k_prep(const float* __restrict__ x,
                       const float* __restrict__ W1,
                       const float* __restrict__ W2) {
    int i = blockIdx.x * blockDim.x + threadIdx.x;
    const int n4 = NN * F_IN / 4;
    if (i < n4) {
        float4 v = ((const float4*)x)[i];
        __half2 a = __float22half2_rn(make_float2(v.x, v.y));
        __half2 b = __float22half2_rn(make_float2(v.z, v.w));
        ((uint2*)g_xb)[i] = make_uint2(*(unsigned*)&a, *(unsigned*)&b);
    }
    if (i < NN) g_cnt[i] = 0;
    if (i < HH) { g_psum[i] = 0.0f; g_pmax[i] = 0.0f; }
    if (i < F_IN * HH) {
        int n = i / F_IN, k = i - n * F_IN;
        g_w1t[i] = __float2half_rn(W1[(size_t)k * HH + n]);
    }
    if (i < HH * HH) {
        int n = i / HH, k = i - n * HH;
        g_w2t[i] = __float2half_rn(W2[(size_t)k * HH + n]);
    }
}

// ----------------------------------------------------------------------------
// Graph build
// ----------------------------------------------------------------------------
__global__ void k_count(const int* __restrict__ col) {
    int e = blockIdx.x * blockDim.x + threadIdx.x;
    if (e < EE) atomicAdd(&g_cnt[col[e]], 1);
}

__global__ void k_blocksum() {
    __shared__ int s[256];
    int t = threadIdx.x, b = blockIdx.x;
    int i = b * SCH + t;
    s[t] = (t < SCH && i < NN) ? g_cnt[i] : 0;
    __syncthreads();
    for (int o = 128; o > 0; o >>= 1) {
        if (t < o) s[t] += s[t + o];
        __syncthreads();
    }
    if (t == 0) g_bsum[b] = s[0];
}

__global__ void k_scanbsum() {
    __shared__ int s[256];
    int t = threadIdx.x;
    s[t] = (t < SBL) ? g_bsum[t] : 0;
    __syncthreads();
    for (int o = 1; o < 256; o <<= 1) {
        int v = (t >= o) ? s[t - o] : 0;
        __syncthreads();
        s[t] += v;
        __syncthreads();
    }
    g_boff[t] = (t == 0) ? 0 : s[t - 1];
    if (t == 0) g_rowptr[NN] = EE;
}

__global__ void k_rowptr() {
    __shared__ int s[256];
    int t = threadIdx.x, b = blockIdx.x;
    int i = b * SCH + t;
    int c = (t < SCH && i < NN) ? g_cnt[i] : 0;
    s[t] = c;
    __syncthreads();
    for (int o = 1; o < 256; o <<= 1) {
        int v = (t >= o) ? s[t - o] : 0;
        __syncthreads();
        s[t] += v;
        __syncthreads();
    }
    if (t < SCH && i < NN) {
        int excl = g_boff[b] + s[t] - c;
        g_rowptr[i] = excl;
        g_cursor[i] = excl;
        g_dinv[i]   = rsqrtf((float)c + 1.0f);
    }
}

__global__ void k_fill(const int* __restrict__ row, const int* __restrict__ col) {
    int e = blockIdx.x * blockDim.x + threadIdx.x;
    if (e < EE) {
        int c = col[e];
        int p = atomicAdd(&g_cursor[c], 1);
        g_csr[p] = row[e];
    }
}

// ----------------------------------------------------------------------------
// Aggregation layer 1: fp16 in (128 feat), fp32 accum, fp16 out. warp/node.
// ----------------------------------------------------------------------------
__global__ void k_agg_b128(const __half* __restrict__ X, __half* __restrict__ out) {
    int w = (blockIdx.x * blockDim.x + threadIdx.x) >> 5;
    int lane = threadIdx.x & 31;
    if (w >= NN) return;
    const uint2* Xv = (const uint2*)X;
    float dc = g_dinv[w];
    float acc[4];
    {
        uint2 u = __ldg(&Xv[(size_t)w * 32 + lane]);
        float2 f0 = __half22float2(*(__half2*)&u.x);
        float2 f1 = __half22float2(*(__half2*)&u.y);
        acc[0] = dc * f0.x; acc[1] = dc * f0.y; acc[2] = dc * f1.x; acc[3] = dc * f1.y;
    }
    int beg = g_rowptr[w], end = g_rowptr[w + 1];
    for (int e0 = beg; e0 < end; e0 += 32) {
        int m = end - e0; if (m > 32) m = 32;
        int r = 0; float dr = 0.0f;
        if (lane < m) { r = g_csr[e0 + lane]; dr = __ldg(&g_dinv[r]); }
        for (int i = 0; i < m; i++) {
            int   ri  = __shfl_sync(0xffffffffu, r, i);
            float dri = __shfl_sync(0xffffffffu, dr, i);
            uint2 u = __ldg(&Xv[(size_t)ri * 32 + lane]);
            float2 f0 = __half22float2(*(__half2*)&u.x);
            float2 f1 = __half22float2(*(__half2*)&u.y);
            acc[0] += dri * f0.x; acc[1] += dri * f0.y;
            acc[2] += dri * f1.x; acc[3] += dri * f1.y;
        }
    }
    __half2 p0 = __float22half2_rn(make_float2(dc * acc[0], dc * acc[1]));
    __half2 p1 = __float22half2_rn(make_float2(dc * acc[2], dc * acc[3]));
    ((uint2*)out)[(size_t)w * 32 + lane] = make_uint2(*(unsigned*)&p0, *(unsigned*)&p1);
}

// ----------------------------------------------------------------------------
// Aggregation layer 2: fp8 e4m3 in (256 feat = 256B/row), fp32 accum, fp16 out.
// warp/node; lane j covers features 8j..8j+7 (uint2 = 8 fp8 per lane).
// ----------------------------------------------------------------------------
__global__ void k_agg_f8(const uint8_t* __restrict__ X, __half* __restrict__ out) {
    int w = (blockIdx.x * blockDim.x + threadIdx.x) >> 5;
    int lane = threadIdx.x & 31;
    if (w >= NN) return;
    const uint2* Xv = (const uint2*)X;   // 32 uint2 per 256-fp8 row
    float dc = g_dinv[w];
    float acc[8];
    {
        uint2 u = __ldg(&Xv[(size_t)w * 32 + lane]);
        float2 f0 = e4m3x2_2f((unsigned short)(u.x & 0xffff));
        float2 f1 = e4m3x2_2f((unsigned short)(u.x >> 16));
        float2 f2 = e4m3x2_2f((unsigned short)(u.y & 0xffff));
        float2 f3 = e4m3x2_2f((unsigned short)(u.y >> 16));
        acc[0] = dc * f0.x; acc[1] = dc * f0.y; acc[2] = dc * f1.x; acc[3] = dc * f1.y;
        acc[4] = dc * f2.x; acc[5] = dc * f2.y; acc[6] = dc * f3.x; acc[7] = dc * f3.y;
    }
    int beg = g_rowptr[w], end = g_rowptr[w + 1];
    for (int e0 = beg; e0 < end; e0 += 32) {
        int m = end - e0; if (m > 32) m = 32;
        int r = 0; float dr = 0.0f;
        if (lane < m) { r = g_csr[e0 + lane]; dr = __ldg(&g_dinv[r]); }
        for (int i = 0; i < m; i++) {
            int   ri  = __shfl_sync(0xffffffffu, r, i);
            float dri = __shfl_sync(0xffffffffu, dr, i);
            uint2 u = __ldg(&Xv[(size_t)ri * 32 + lane]);
            float2 f0 = e4m3x2_2f((unsigned short)(u.x & 0xffff));
            float2 f1 = e4m3x2_2f((unsigned short)(u.x >> 16));
            float2 f2 = e4m3x2_2f((unsigned short)(u.y & 0xffff));
            float2 f3 = e4m3x2_2f((unsigned short)(u.y >> 16));
            acc[0] += dri * f0.x; acc[1] += dri * f0.y;
            acc[2] += dri * f1.x; acc[3] += dri * f1.y;
            acc[4] += dri * f2.x; acc[5] += dri * f2.y;
            acc[6] += dri * f3.x; acc[7] += dri * f3.y;
        }
    }
    __half2 p0 = __float22half2_rn(make_float2(dc * acc[0], dc * acc[1]));
    __half2 p1 = __float22half2_rn(make_float2(dc * acc[2], dc * acc[3]));
    __half2 p2 = __float22half2_rn(make_float2(dc * acc[4], dc * acc[5]));
    __half2 p3 = __float22half2_rn(make_float2(dc * acc[6], dc * acc[7]));
    ((uint4*)out)[(size_t)w * 32 + lane] =
        make_uint4(*(unsigned*)&p0, *(unsigned*)&p1, *(unsigned*)&p2, *(unsigned*)&p3);
}

// ----------------------------------------------------------------------------
// fp16 tensor-core GEMM: 128x128 block, k-chunk 32, 2-stage cp.async,
// mma.m16n8k16.f16 (fp32 accum), 8 warps (warp tile 64x32).
// MODE 0: C = relu(A@B + bias) written as fp8 e4m3 (h1).
// MODE 1: no C; per-column sum/max of relu(A@B + bias) -> g_psum/g_pmax.
// ----------------------------------------------------------------------------
#define SP 40

__device__ __forceinline__ void cpa16(uint32_t dst, const void* src, int sz) {
    asm volatile("cp.async.cg.shared.global [%0], [%1], 16, %2;\n"
                 :: "r"(dst), "l"(src), "r"(sz));
}

__device__ __forceinline__ void mma_fp16(float& c0, float& c1, float& c2, float& c3,
                                         unsigned a0, unsigned a1, unsigned a2, unsigned a3,
                                         unsigned b0, unsigned b1) {
    asm volatile(
        "mma.sync.aligned.m16n8k16.row.col.f32.f16.f16.f32 "
        "{%0,%1,%2,%3}, {%4,%5,%6,%7}, {%8,%9}, {%0,%1,%2,%3};"
        : "+f"(c0), "+f"(c1), "+f"(c2), "+f"(c3)
        : "r"(a0), "r"(a1), "r"(a2), "r"(a3), "r"(b0), "r"(b1));
}

template <int MODE>
__global__ __launch_bounds__(256) void k_gemm_fp16(
    const __half* __restrict__ A, const __half* __restrict__ Bt,
    const float* __restrict__ bias, void* __restrict__ Cout,
    int M, int K, int Nc)
{
    __shared__ __align__(16) __half As[2][128 * SP];
    __shared__ __align__(16) __half Bs[2][128 * SP];

    const int tid  = threadIdx.x;
    const int lane = tid & 31;
    const int warp = tid >> 5;
    const int wm   = warp & 1;
    const int wn   = warp >> 1;
    const int g    = lane >> 2;
    const int tig  = lane & 3;
    const int rowBase = blockIdx.y * 128;
    const int colBase = blockIdx.x * 128;

    const int lrow = tid >> 1;
    const int lq   = (tid & 1) * 2;
    const int dA0  = (lrow * SP + lq * 8) * 2;
    const int dA1  = dA0 + 16;

    uint32_t as0 = (uint32_t)__cvta_generic_to_shared(&As[0][0]);
    uint32_t as1 = (uint32_t)__cvta_generic_to_shared(&As[1][0]);
    uint32_t bs0 = (uint32_t)__cvta_generic_to_shared(&Bs[0][0]);
    uint32_t bs1 = (uint32_t)__cvta_generic_to_shared(&Bs[1][0]);

    const int rA = rowBase + lrow;
    const int okA = (rA < M) ? 16 : 0;
    const __half* srcA = A + (size_t)((rA < M) ? rA : 0) * K + lq * 8;
    const __half* srcB = Bt + (size_t)(colBase + lrow) * K + lq * 8;

    float acc[4][4][4];
#pragma unroll
    for (int mt = 0; mt < 4; mt++)
#pragma unroll
        for (int nt = 0; nt < 4; nt++)
#pragma unroll
            for (int q = 0; q < 4; q++) acc[mt][nt][q] = 0.0f;

#define ISSUE(stage, k0)                                                       \
    {                                                                          \
        uint32_t ad = (stage) ? as1 : as0;                                     \
        uint32_t bd = (stage) ? bs1 : bs0;                                     \
        cpa16(ad + dA0, srcA + (k0), okA);                                     \
        cpa16(ad + dA1, srcA + (k0) + 8, okA);                                 \
        cpa16(bd + dA0, srcB + (k0), 16);                                      \
        cpa16(bd + dA1, srcB + (k0) + 8, 16);                                  \
        asm volatile("cp.async.commit_group;\n" ::: "memory");                 \
    }

#define COMPUTE(stage)                                                         \
    {                                                                          \
        const __half* Ap = As[stage];                                          \
        const __half* Bp = Bs[stage];                                          \
        _Pragma("unroll")                                                      \
        for (int ks = 0; ks < 32; ks += 16) {                                  \
            unsigned af[4][4], bf[4][2];                                       \
            _Pragma("unroll")                                                  \
            for (int mt = 0; mt < 4; mt++) {                                   \
                int m0 = wm * 64 + mt * 16;                                    \
                af[mt][0] = *(const unsigned*)&Ap[(m0 + g) * SP + ks + tig * 2];      \
                af[mt][1] = *(const unsigned*)&Ap[(m0 + g + 8) * SP + ks + tig * 2];  \
                af[mt][2] = *(const unsigned*)&Ap[(m0 + g) * SP + ks + tig * 2 + 8];  \
                af[mt][3] = *(const unsigned*)&Ap[(m0 + g + 8) * SP + ks + tig * 2 + 8]; \
            }                                                                  \
            _Pragma("unroll")                                                  \
            for (int nt = 0; nt < 4; nt++) {                                   \
                int n0 = wn * 32 + nt * 8;                                     \
                bf[nt][0] = *(const unsigned*)&Bp[(n0 + g) * SP + ks + tig * 2];      \
                bf[nt][1] = *(const unsigned*)&Bp[(n0 + g) * SP + ks + tig * 2 + 8];  \
            }                                                                  \
            _Pragma("unroll")                                                  \
            for (int mt = 0; mt < 4; mt++)                                     \
                _Pragma("unroll")                                              \
                for (int nt = 0; nt < 4; nt++)                                 \
                    mma_fp16(acc[mt][nt][0], acc[mt][nt][1],                   \
                             acc[mt][nt][2], acc[mt][nt][3],                   \
                             af[mt][0], af[mt][1], af[mt][2], af[mt][3],       \
                             bf[nt][0], bf[nt][1]);                            \
        }                                                                      \
    }

    const int nIter = K >> 5;
    ISSUE(0, 0);
    for (int it = 0; it < nIter; it++) {
        if (it + 1 < nIter) {
            ISSUE((it + 1) & 1, (it + 1) * 32);
            asm volatile("cp.async.wait_group 1;\n" ::: "memory");
        } else {
            asm volatile("cp.async.wait_group 0;\n" ::: "memory");
        }
        __syncthreads();
        COMPUTE(it & 1);
        __syncthreads();
    }

    if (MODE == 0) {
        uint8_t* C8 = (uint8_t*)Cout;
#pragma unroll
        for (int mt = 0; mt < 4; mt++) {
            int r0 = rowBase + wm * 64 + mt * 16 + g;
            int r1 = r0 + 8;
#pragma unroll
            for (int nt = 0; nt < 4; nt++) {
                int cidx = colBase + wn * 32 + nt * 8 + tig * 2;
                float bx = bias[cidx], by = bias[cidx + 1];
                if (r0 < M) {
                    unsigned short p = f2e4m3x2(fmaxf(acc[mt][nt][1] + by, 0.0f),
                                                fmaxf(acc[mt][nt][0] + bx, 0.0f));
                    *(unsigned short*)(C8 + (size_t)r0 * Nc + cidx) = p;
                }
                if (r1 < M) {
                    unsigned short p = f2e4m3x2(fmaxf(acc[mt][nt][3] + by, 0.0f),
                                                fmaxf(acc[mt][nt][2] + bx, 0.0f));
                    *(unsigned short*)(C8 + (size_t)r1 * Nc + cidx) = p;
                }
            }
        }
    } else {
        // fused global pooling
        float ps[4][2], pm[4][2];
#pragma unroll
        for (int nt = 0; nt < 4; nt++) { ps[nt][0] = ps[nt][1] = 0.0f; pm[nt][0] = pm[nt][1] = 0.0f; }
#pragma unroll
        for (int mt = 0; mt < 4; mt++) {
            int r0 = rowBase + wm * 64 + mt * 16 + g;
            int r1 = r0 + 8;
#pragma unroll
            for (int nt = 0; nt < 4; nt++) {
                int cidx = colBase + wn * 32 + nt * 8 + tig * 2;
                float bx = bias[cidx], by = bias[cidx + 1];
                if (r0 < M) {
                    float v0 = fmaxf(acc[mt][nt][0] + bx, 0.0f);
                    float v1 = fmaxf(acc[mt][nt][1] + by, 0.0f);
                    ps[nt][0] += v0; ps[nt][1] += v1;
                    pm[nt][0] = fmaxf(pm[nt][0], v0); pm[nt][1] = fmaxf(pm[nt][1], v1);
                }
                if (r1 < M) {
                    float v0 = fmaxf(acc[mt][nt][2] + bx, 0.0f);
                    float v1 = fmaxf(acc[mt][nt][3] + by, 0.0f);
                    ps[nt][0] += v0; ps[nt][1] += v1;
                    pm[nt][0] = fmaxf(pm[nt][0], v0); pm[nt][1] = fmaxf(pm[nt][1], v1);
                }
            }
        }
#pragma unroll
        for (int o = 4; o <= 16; o <<= 1) {
#pragma unroll
            for (int nt = 0; nt < 4; nt++) {
#pragma unroll
                for (int p = 0; p < 2; p++) {
                    ps[nt][p] += __shfl_xor_sync(0xffffffffu, ps[nt][p], o);
                    pm[nt][p] = fmaxf(pm[nt][p], __shfl_xor_sync(0xffffffffu, pm[nt][p], o));
                }
            }
        }
        if (lane < 4) {
#pragma unroll
            for (int nt = 0; nt < 4; nt++) {
#pragma unroll
                for (int p = 0; p < 2; p++) {
                    int col = colBase + wn * 32 + nt * 8 + lane * 2 + p;
                    atomicAdd(&g_psum[col], ps[nt][p]);
                    atomicMax((int*)&g_pmax[col], __float_as_int(pm[nt][p]));
                }
            }
        }
    }
#undef ISSUE
#undef COMPUTE
}

// ----------------------------------------------------------------------------
// Head
// ----------------------------------------------------------------------------
__global__ void k_final(const float* __restrict__ Wlin, const float* __restrict__ blin,
                        float* __restrict__ out) {
    int w = threadIdx.x >> 5;
    int lane = threadIdx.x & 31;
    if (w >= AA) return;
    const float invN = 1.0f / (float)NN;
    float acc = 0.0f;
    for (int j = lane; j < HH; j += 32) {
        float s = g_psum[j];
        float m = g_pmax[j];
        acc += s * invN * Wlin[(size_t)j * AA + w]
             + m        * Wlin[(size_t)(HH + j) * AA + w]
             + s        * Wlin[(size_t)(2 * HH + j) * AA + w];
    }
#pragma unroll
    for (int o = 16; o > 0; o >>= 1) acc += __shfl_down_sync(0xffffffffu, acc, o);
    if (lane == 0) out[w] = blin[w] + acc;
}

// ----------------------------------------------------------------------------
// Launch
// ----------------------------------------------------------------------------
extern "C" void kernel_launch(void* const* d_in, const int* in_sizes, int n_in,
                              void* d_out, int out_size) {
    const float* x    = (const float*)d_in[0];
    const int*   ei   = (const int*)d_in[1];
    const float* W1   = (const float*)d_in[2];
    const float* b1   = (const float*)d_in[3];
    const float* W2   = (const float*)d_in[4];
    const float* b2   = (const float*)d_in[5];
    const float* Wlin = (const float*)d_in[6];
    const float* blin = (const float*)d_in[7];
    float*       out  = (float*)d_out;

    const int* erow = ei;
    const int* ecol = ei + EE;

    __half *xb, *a1, *a2, *w1t, *w2t;
    uint8_t* h8;
    cudaGetSymbolAddress((void**)&xb, g_xb);
    cudaGetSymbolAddress((void**)&a1, g_a1);
    cudaGetSymbolAddress((void**)&h8, g_h8);
    cudaGetSymbolAddress((void**)&a2, g_a2);
    cudaGetSymbolAddress((void**)&w1t, g_w1t);
    cudaGetSymbolAddress((void**)&w2t, g_w2t);

    // prep (cnt/psum/pmax zero + casts + weight transposes)
    k_prep<<<(NN * F_IN / 4 + 255) / 256, 256>>>(x, W1, W2);

    // graph structure
    k_count<<<(EE + 255) / 256, 256>>>(ecol);
    k_blocksum<<<SBL, 256>>>();
    k_scanbsum<<<1, 256>>>();
    k_rowptr<<<SBL, 256>>>();
    k_fill<<<(EE + 255) / 256, 256>>>(erow, ecol);

    dim3 ggrid(HH / 128, (NN + 127) / 128);
    const int aggBlocks = (NN + 7) / 8;  // 8 warps per block

    // layer 1: agg (fp16) -> GEMM -> h1 stored fp8
    k_agg_b128<<<aggBlocks, 256>>>(xb, a1);
    k_gemm_fp16<0><<<ggrid, 256>>>(a1, w1t, b1, h8, NN, F_IN, HH);

    // layer 2: agg (fp8 gather) -> GEMM with fused pooling
    k_agg_f8<<<aggBlocks, 256>>>(h8, a2);
    k_gemm_fp16<1><<<ggrid, 256>>>(a2, w2t, b2, nullptr, NN, HH, HH);

    // head
    k_final<<<1, 160>>>(Wlin, blin, out);
}